// round 8
// baseline (speedup 1.0000x reference)
#include <cuda_runtime.h>
#include <cuda_bf16.h>
#include <cuda_fp16.h>
#include <cstdint>
#include <cstring>

// GCNConv: out = D_in^{-1/2} * A * (D_out^{-1/2} * (X @ W)) + bias
// Stage 0: bake W -> fp16 frag layout (32KB global, L1-resident in GEMM)
// Stage 1: zero-smem fp16 2-term compensated mma.sync GEMM
//          h = (X @ W) * out_norm -> fp16 scratch
//          (a_hi + a_lo) * b_hi  ==  a * fp16(W); only W-rounding error remains
// Stage 2: gather-aggregate (fp16 reads)

#define MAX_N 100000

__device__ __half g_h[(size_t)MAX_N * 128];
// frag layout: [ntile 0..15][kstep 0..7][lane 0..31] = {fh0, fh1} (fp16x2 each)
__device__ uint2  g_wfrag[16 * 8 * 32];

// ---------------------------------------------------------------------------
// helpers
// ---------------------------------------------------------------------------
__device__ __forceinline__ unsigned h2u(__half2 v) {
    unsigned r;
    memcpy(&r, &v, 4);
    return r;
}

// split float2 -> fp16x2 hi + fp16x2 lo (residual)
__device__ __forceinline__ void split_f16x2(float2 v, unsigned& hi, unsigned& lo) {
    __half2 h = __floats2half2_rn(v.x, v.y);
    float2 hf = __half22float2(h);
    __half2 l = __floats2half2_rn(v.x - hf.x, v.y - hf.y);
    hi = h2u(h);
    lo = h2u(l);
}

__device__ __forceinline__ void mma_f16(float* c, const unsigned* a,
                                        unsigned b0, unsigned b1) {
    asm volatile(
        "mma.sync.aligned.m16n8k16.row.col.f32.f16.f16.f32 "
        "{%0,%1,%2,%3}, {%4,%5,%6,%7}, {%8,%9}, {%0,%1,%2,%3};"
        : "+f"(c[0]), "+f"(c[1]), "+f"(c[2]), "+f"(c[3])
        : "r"(a[0]), "r"(a[1]), "r"(a[2]), "r"(a[3]), "r"(b0), "r"(b1));
}

// ---------------------------------------------------------------------------
// Stage 0: bake W [k][n] fp32 row-major into per-thread fp16 frag layout.
// (ntile, kstep, lane): lg=lane>>2, lt=lane&3, n = ntile*8+lg, k0=kstep*16+2lt
//   fh0 = fp16x2(W[k0][n], W[k0+1][n]);  fh1 = fp16x2(W[k0+8][n], W[k0+9][n])
// ---------------------------------------------------------------------------
__global__ __launch_bounds__(256) void wfrag_kernel(const float* __restrict__ w) {
    int idx = blockIdx.x * 256 + threadIdx.x;   // 0..4095
    int lane  = idx & 31;
    int kstep = (idx >> 5) & 7;
    int ntile = idx >> 8;
    int lg = lane >> 2;
    int lt = lane & 3;
    int nn = ntile * 8 + lg;
    int k0 = kstep * 16 + 2 * lt;

    float f00 = w[(k0    ) * 128 + nn];
    float f01 = w[(k0 + 1) * 128 + nn];
    float f10 = w[(k0 + 8) * 128 + nn];
    float f11 = w[(k0 + 9) * 128 + nn];

    unsigned fh0 = h2u(__floats2half2_rn(f00, f01));
    unsigned fh1 = h2u(__floats2half2_rn(f10, f11));

    g_wfrag[idx] = make_uint2(fh0, fh1);
}

// ---------------------------------------------------------------------------
// Stage 1 GEMM: zero smem. Block = 128 rows, 8 warps; warp owns rows
// [wid*16, wid*16+16) x cols [0,128) = 16 n8-tiles. 2-term fp16 compensation.
// A-frags straight from global (each row read once per grid), B-frags from
// L1-resident g_wfrag (32KB, shared by all warps on the SM).
// ---------------------------------------------------------------------------
__global__ __launch_bounds__(256, 2) void gemm_mma_kernel(
    const float* __restrict__ x,       // [n,128]
    const uint2* __restrict__ wfrag,   // baked W frags
    const int*   __restrict__ colptr,  // [n+1]
    __half*      __restrict__ h,       // [n,128]
    int n)
{
    const int tid  = threadIdx.x;
    const int wid  = tid >> 5;
    const int lane = tid & 31;
    const int lg   = lane >> 2;
    const int lt   = lane & 3;
    const int rowbase = blockIdx.x * 128 + wid * 16;

    const int r0 = rowbase + lg;       // rows r0, r0+8
    const int r1 = r0 + 8;
    const bool v0 = r0 < n, v1 = r1 < n;

    const float2* xr0 = reinterpret_cast<const float2*>(x + (size_t)r0 * 128);
    const float2* xr1 = reinterpret_cast<const float2*>(x + (size_t)r1 * 128);

    float acc[16][4];
    #pragma unroll
    for (int nt = 0; nt < 16; nt++)
        #pragma unroll
        for (int j = 0; j < 4; j++)
            acc[nt][j] = 0.f;

    const float2 z2 = make_float2(0.f, 0.f);

    // A prefetch: j0=(r0,klo) j1=(r1,klo) j2=(r0,khi) j3=(r1,khi)
    float2 pa[4];
    pa[0] = v0 ? xr0[lt]     : z2;
    pa[1] = v1 ? xr1[lt]     : z2;
    pa[2] = v0 ? xr0[lt + 4] : z2;
    pa[3] = v1 ? xr1[lt + 4] : z2;

    const uint2* wf = wfrag + lane;

    #pragma unroll
    for (int s = 0; s < 8; s++) {
        unsigned a_hi[4], a_lo[4];
        #pragma unroll
        for (int j = 0; j < 4; j++)
            split_f16x2(pa[j], a_hi[j], a_lo[j]);

        if (s < 7) {
            const int kq = (s + 1) * 8 + lt;
            pa[0] = v0 ? xr0[kq]     : z2;
            pa[1] = v1 ? xr1[kq]     : z2;
            pa[2] = v0 ? xr0[kq + 4] : z2;
            pa[3] = v1 ? xr1[kq + 4] : z2;
        }

        #pragma unroll
        for (int nt = 0; nt < 16; nt++) {
            uint2 b = wf[(nt * 8 + s) * 32];
            mma_f16(acc[nt], a_hi, b.x, b.y);   // a_hi * b_hi
            mma_f16(acc[nt], a_lo, b.x, b.y);   // a_lo * b_hi
        }
    }

    // --- epilogue: scale by out_norm (1/sqrt(out-degree)), fp16 stores ---
    float s0 = 0.f, s1 = 0.f;
    if (v0) {
        float d = (float)(colptr[r0 + 1] - colptr[r0]);
        s0 = (d > 0.f) ? rsqrtf(d) : 0.f;
    }
    if (v1) {
        float d = (float)(colptr[r1 + 1] - colptr[r1]);
        s1 = (d > 0.f) ? rsqrtf(d) : 0.f;
    }

    #pragma unroll
    for (int nt = 0; nt < 16; nt++) {
        const int col = nt * 8 + 2 * lt;
        if (v0) {
            __half2 p = __floats2half2_rn(acc[nt][0] * s0, acc[nt][1] * s0);
            *reinterpret_cast<unsigned*>(&h[(size_t)r0 * 128 + col]) = h2u(p);
        }
        if (v1) {
            __half2 p = __floats2half2_rn(acc[nt][2] * s1, acc[nt][3] * s1);
            *reinterpret_cast<unsigned*>(&h[(size_t)r1 * 128 + col]) = h2u(p);
        }
    }
}

// ---------------------------------------------------------------------------
// Stage 2: aggregation. 8 nodes/block (256 thr), 32 lanes/node, uint2 fp16
// loads, fp32 accumulate.
// ---------------------------------------------------------------------------
__global__ __launch_bounds__(256) void aggregate_kernel(
    const __half* __restrict__ h,
    const int*    __restrict__ rowptr,
    const int*    __restrict__ colind,
    const float*  __restrict__ bias,
    float*        __restrict__ out,
    int n)
{
    const int node = blockIdx.x * 8 + (threadIdx.x >> 5);
    const int lane = threadIdx.x & 31;
    if (node >= n) return;

    const int beg = rowptr[node];
    const int end = rowptr[node + 1];
    const uint2* h2 = reinterpret_cast<const uint2*>(h);

    float4 acc = make_float4(0.f, 0.f, 0.f, 0.f);

    int e = beg;
    for (; e + 4 <= end; e += 4) {
        int i0 = __ldg(&colind[e + 0]);
        int i1 = __ldg(&colind[e + 1]);
        int i2 = __ldg(&colind[e + 2]);
        int i3 = __ldg(&colind[e + 3]);
        uint2 u0 = h2[(size_t)i0 * 32 + lane];
        uint2 u1 = h2[(size_t)i1 * 32 + lane];
        uint2 u2 = h2[(size_t)i2 * 32 + lane];
        uint2 u3 = h2[(size_t)i3 * 32 + lane];
        float2 f;
        f = __half22float2(*reinterpret_cast<__half2*>(&u0.x)); acc.x += f.x; acc.y += f.y;
        f = __half22float2(*reinterpret_cast<__half2*>(&u0.y)); acc.z += f.x; acc.w += f.y;
        f = __half22float2(*reinterpret_cast<__half2*>(&u1.x)); acc.x += f.x; acc.y += f.y;
        f = __half22float2(*reinterpret_cast<__half2*>(&u1.y)); acc.z += f.x; acc.w += f.y;
        f = __half22float2(*reinterpret_cast<__half2*>(&u2.x)); acc.x += f.x; acc.y += f.y;
        f = __half22float2(*reinterpret_cast<__half2*>(&u2.y)); acc.z += f.x; acc.w += f.y;
        f = __half22float2(*reinterpret_cast<__half2*>(&u3.x)); acc.x += f.x; acc.y += f.y;
        f = __half22float2(*reinterpret_cast<__half2*>(&u3.y)); acc.z += f.x; acc.w += f.y;
    }
    for (; e < end; e++) {
        int i0 = __ldg(&colind[e]);
        uint2 u0 = h2[(size_t)i0 * 32 + lane];
        float2 f;
        f = __half22float2(*reinterpret_cast<__half2*>(&u0.x)); acc.x += f.x; acc.y += f.y;
        f = __half22float2(*reinterpret_cast<__half2*>(&u0.y)); acc.z += f.x; acc.w += f.y;
    }

    float deg = (float)(end - beg);
    float s = (deg > 0.f) ? rsqrtf(deg) : 0.f;

    float4 b = reinterpret_cast<const float4*>(bias)[lane];
    float4 o;
    o.x = acc.x * s + b.x;
    o.y = acc.y * s + b.y;
    o.z = acc.z * s + b.z;
    o.w = acc.w * s + b.w;

    reinterpret_cast<float4*>(out)[(size_t)node * 32 + lane] = o;
}

// ---------------------------------------------------------------------------
// launch
// ---------------------------------------------------------------------------
extern "C" void kernel_launch(void* const* d_in, const int* in_sizes, int n_in,
                              void* d_out, int out_size)
{
    const float* x      = (const float*)d_in[0];
    const float* weight = (const float*)d_in[1];
    const float* bias   = (const float*)d_in[2];
    const int*   rowptr = (const int*)  d_in[3];
    const int*   colind = (const int*)  d_in[4];
    const int*   colptr = (const int*)  d_in[5];

    const int n = in_sizes[3] - 1;
    float* out = (float*)d_out;

    __half* h_scratch = nullptr;
    cudaGetSymbolAddress((void**)&h_scratch, g_h);
    uint2* wfrag = nullptr;
    cudaGetSymbolAddress((void**)&wfrag, g_wfrag);

    // Stage 0: bake W frags (4096 uint2)
    wfrag_kernel<<<16, 256>>>(weight);

    // Stage 1: GEMM (128 rows per block)
    int gemm_blocks = (n + 127) / 128;
    gemm_mma_kernel<<<gemm_blocks, 256>>>(x, wfrag, colptr, h_scratch, n);

    // Stage 2: aggregate
    int agg_blocks = (n + 7) / 8;
    aggregate_kernel<<<agg_blocks, 256>>>(h_scratch, rowptr, colind, bias,
                                          out, n);
}

// round 9
// speedup vs baseline: 1.4079x; 1.4079x over previous
#include <cuda_runtime.h>
#include <cuda_bf16.h>
#include <cuda_fp16.h>
#include <cstdint>
#include <cstring>

// GCNConv: out = D_in^{-1/2} * A * (D_out^{-1/2} * (X @ W)) + bias
// Stage 0: bake W -> fp16 hi/lo frag layout (64KB global, L1-resident)
// Stage 1: zero-smem fp16 asymmetric 2-term mma.sync GEMM
//          h = f16(X) @ (W_hi + W_lo) * out_norm -> fp16 scratch
//          (only X's fp16 rounding is dropped: ~2.8e-4)
// Stage 2: gather-aggregate (fp16 reads)

#define MAX_N 100000

__device__ __half g_h[(size_t)MAX_N * 128];
// frag layout: [ntile 0..15][kstep 0..7][lane 0..31] = {bh0, bh1, bl0, bl1}
__device__ uint4  g_wfrag[16 * 8 * 32];

// ---------------------------------------------------------------------------
// helpers
// ---------------------------------------------------------------------------
__device__ __forceinline__ unsigned h2u(__half2 v) {
    unsigned r;
    memcpy(&r, &v, 4);
    return r;
}

__device__ __forceinline__ unsigned cvt_f16x2(float2 v) {
    unsigned r;
    asm("cvt.rn.f16x2.f32 %0, %1, %2;" : "=r"(r) : "f"(v.y), "f"(v.x));
    return r;
}

__device__ __forceinline__ void mma_f16(float* c, const unsigned* a,
                                        unsigned b0, unsigned b1) {
    asm volatile(
        "mma.sync.aligned.m16n8k16.row.col.f32.f16.f16.f32 "
        "{%0,%1,%2,%3}, {%4,%5,%6,%7}, {%8,%9}, {%0,%1,%2,%3};"
        : "+f"(c[0]), "+f"(c[1]), "+f"(c[2]), "+f"(c[3])
        : "r"(a[0]), "r"(a[1]), "r"(a[2]), "r"(a[3]), "r"(b0), "r"(b1));
}

// ---------------------------------------------------------------------------
// Stage 0: bake W [k][n] fp32 into per-thread fp16 hi/lo frag layout.
// (ntile, kstep, lane): lg=lane>>2, lt=lane&3, n = ntile*8+lg, k0=kstep*16+2lt
//   bh0 = f16x2(W[k0][n], W[k0+1][n]);   bh1 = f16x2(W[k0+8][n], W[k0+9][n])
//   bl0/bl1 = f16 residuals of the same elements
// ---------------------------------------------------------------------------
__global__ __launch_bounds__(256) void wfrag_kernel(const float* __restrict__ w) {
    int idx = blockIdx.x * 256 + threadIdx.x;   // 0..4095
    int lane  = idx & 31;
    int kstep = (idx >> 5) & 7;
    int ntile = idx >> 8;
    int lg = lane >> 2;
    int lt = lane & 3;
    int nn = ntile * 8 + lg;
    int k0 = kstep * 16 + 2 * lt;

    float f00 = w[(k0    ) * 128 + nn];
    float f01 = w[(k0 + 1) * 128 + nn];
    float f10 = w[(k0 + 8) * 128 + nn];
    float f11 = w[(k0 + 9) * 128 + nn];

    __half2 h0 = __floats2half2_rn(f00, f01);
    __half2 h1 = __floats2half2_rn(f10, f11);
    float2 h0f = __half22float2(h0);
    float2 h1f = __half22float2(h1);
    __half2 l0 = __floats2half2_rn(f00 - h0f.x, f01 - h0f.y);
    __half2 l1 = __floats2half2_rn(f10 - h1f.x, f11 - h1f.y);

    g_wfrag[idx] = make_uint4(h2u(h0), h2u(h1), h2u(l0), h2u(l1));
}

// ---------------------------------------------------------------------------
// Stage 1 GEMM: zero smem. Block = 128 rows, 8 warps; warp owns rows
// [wid*16, wid*16+16) x cols [0,128) = 16 n8-tiles.
// A: single fp16 conversion (one cvt per frag reg). B: baked hi+lo, 2 MMAs/tile.
// ---------------------------------------------------------------------------
__global__ __launch_bounds__(256, 2) void gemm_mma_kernel(
    const float* __restrict__ x,       // [n,128]
    const uint4* __restrict__ wfrag,   // baked W frags
    const int*   __restrict__ colptr,  // [n+1]
    __half*      __restrict__ h,       // [n,128]
    int n)
{
    const int tid  = threadIdx.x;
    const int wid  = tid >> 5;
    const int lane = tid & 31;
    const int lg   = lane >> 2;
    const int lt   = lane & 3;
    const int rowbase = blockIdx.x * 128 + wid * 16;

    const int r0 = rowbase + lg;       // rows r0, r0+8
    const int r1 = r0 + 8;
    const bool v0 = r0 < n, v1 = r1 < n;

    const float2* xr0 = reinterpret_cast<const float2*>(x + (size_t)r0 * 128);
    const float2* xr1 = reinterpret_cast<const float2*>(x + (size_t)r1 * 128);

    float acc[16][4];
    #pragma unroll
    for (int nt = 0; nt < 16; nt++)
        #pragma unroll
        for (int j = 0; j < 4; j++)
            acc[nt][j] = 0.f;

    const float2 z2 = make_float2(0.f, 0.f);

    // A prefetch: j0=(r0,klo) j1=(r1,klo) j2=(r0,khi) j3=(r1,khi)
    float2 pa[4];
    pa[0] = v0 ? xr0[lt]     : z2;
    pa[1] = v1 ? xr1[lt]     : z2;
    pa[2] = v0 ? xr0[lt + 4] : z2;
    pa[3] = v1 ? xr1[lt + 4] : z2;

    const uint4* wf = wfrag + lane;

    #pragma unroll
    for (int s = 0; s < 8; s++) {
        unsigned a[4];
        #pragma unroll
        for (int j = 0; j < 4; j++)
            a[j] = cvt_f16x2(pa[j]);

        if (s < 7) {
            const int kq = (s + 1) * 8 + lt;
            pa[0] = v0 ? xr0[kq]     : z2;
            pa[1] = v1 ? xr1[kq]     : z2;
            pa[2] = v0 ? xr0[kq + 4] : z2;
            pa[3] = v1 ? xr1[kq + 4] : z2;
        }

        #pragma unroll
        for (int nt = 0; nt < 16; nt++) {
            uint4 b = wf[(nt * 8 + s) * 32];
            mma_f16(acc[nt], a, b.x, b.y);   // a * b_hi
            mma_f16(acc[nt], a, b.z, b.w);   // a * b_lo
        }
    }

    // --- epilogue: scale by out_norm (1/sqrt(out-degree)), fp16 stores ---
    float s0 = 0.f, s1 = 0.f;
    if (v0) {
        float d = (float)(colptr[r0 + 1] - colptr[r0]);
        s0 = (d > 0.f) ? rsqrtf(d) : 0.f;
    }
    if (v1) {
        float d = (float)(colptr[r1 + 1] - colptr[r1]);
        s1 = (d > 0.f) ? rsqrtf(d) : 0.f;
    }

    #pragma unroll
    for (int nt = 0; nt < 16; nt++) {
        const int col = nt * 8 + 2 * lt;
        if (v0) {
            __half2 p = __floats2half2_rn(acc[nt][0] * s0, acc[nt][1] * s0);
            *reinterpret_cast<unsigned*>(&h[(size_t)r0 * 128 + col]) = h2u(p);
        }
        if (v1) {
            __half2 p = __floats2half2_rn(acc[nt][2] * s1, acc[nt][3] * s1);
            *reinterpret_cast<unsigned*>(&h[(size_t)r1 * 128 + col]) = h2u(p);
        }
    }
}

// ---------------------------------------------------------------------------
// Stage 2: aggregation. 8 nodes/block (256 thr), 32 lanes/node, uint2 fp16
// loads, fp32 accumulate.
// ---------------------------------------------------------------------------
__global__ __launch_bounds__(256) void aggregate_kernel(
    const __half* __restrict__ h,
    const int*    __restrict__ rowptr,
    const int*    __restrict__ colind,
    const float*  __restrict__ bias,
    float*        __restrict__ out,
    int n)
{
    const int node = blockIdx.x * 8 + (threadIdx.x >> 5);
    const int lane = threadIdx.x & 31;
    if (node >= n) return;

    const int beg = rowptr[node];
    const int end = rowptr[node + 1];
    const uint2* h2 = reinterpret_cast<const uint2*>(h);

    float4 acc = make_float4(0.f, 0.f, 0.f, 0.f);

    int e = beg;
    for (; e + 4 <= end; e += 4) {
        int i0 = __ldg(&colind[e + 0]);
        int i1 = __ldg(&colind[e + 1]);
        int i2 = __ldg(&colind[e + 2]);
        int i3 = __ldg(&colind[e + 3]);
        uint2 u0 = h2[(size_t)i0 * 32 + lane];
        uint2 u1 = h2[(size_t)i1 * 32 + lane];
        uint2 u2 = h2[(size_t)i2 * 32 + lane];
        uint2 u3 = h2[(size_t)i3 * 32 + lane];
        float2 f;
        f = __half22float2(*reinterpret_cast<__half2*>(&u0.x)); acc.x += f.x; acc.y += f.y;
        f = __half22float2(*reinterpret_cast<__half2*>(&u0.y)); acc.z += f.x; acc.w += f.y;
        f = __half22float2(*reinterpret_cast<__half2*>(&u1.x)); acc.x += f.x; acc.y += f.y;
        f = __half22float2(*reinterpret_cast<__half2*>(&u1.y)); acc.z += f.x; acc.w += f.y;
        f = __half22float2(*reinterpret_cast<__half2*>(&u2.x)); acc.x += f.x; acc.y += f.y;
        f = __half22float2(*reinterpret_cast<__half2*>(&u2.y)); acc.z += f.x; acc.w += f.y;
        f = __half22float2(*reinterpret_cast<__half2*>(&u3.x)); acc.x += f.x; acc.y += f.y;
        f = __half22float2(*reinterpret_cast<__half2*>(&u3.y)); acc.z += f.x; acc.w += f.y;
    }
    for (; e < end; e++) {
        int i0 = __ldg(&colind[e]);
        uint2 u0 = h2[(size_t)i0 * 32 + lane];
        float2 f;
        f = __half22float2(*reinterpret_cast<__half2*>(&u0.x)); acc.x += f.x; acc.y += f.y;
        f = __half22float2(*reinterpret_cast<__half2*>(&u0.y)); acc.z += f.x; acc.w += f.y;
    }

    float deg = (float)(end - beg);
    float s = (deg > 0.f) ? rsqrtf(deg) : 0.f;

    float4 b = reinterpret_cast<const float4*>(bias)[lane];
    float4 o;
    o.x = acc.x * s + b.x;
    o.y = acc.y * s + b.y;
    o.z = acc.z * s + b.z;
    o.w = acc.w * s + b.w;

    reinterpret_cast<float4*>(out)[(size_t)node * 32 + lane] = o;
}

// ---------------------------------------------------------------------------
// launch
// ---------------------------------------------------------------------------
extern "C" void kernel_launch(void* const* d_in, const int* in_sizes, int n_in,
                              void* d_out, int out_size)
{
    const float* x      = (const float*)d_in[0];
    const float* weight = (const float*)d_in[1];
    const float* bias   = (const float*)d_in[2];
    const int*   rowptr = (const int*)  d_in[3];
    const int*   colind = (const int*)  d_in[4];
    const int*   colptr = (const int*)  d_in[5];

    const int n = in_sizes[3] - 1;
    float* out = (float*)d_out;

    __half* h_scratch = nullptr;
    cudaGetSymbolAddress((void**)&h_scratch, g_h);
    uint4* wfrag = nullptr;
    cudaGetSymbolAddress((void**)&wfrag, g_wfrag);

    // Stage 0: bake W frags (4096 uint4)
    wfrag_kernel<<<16, 256>>>(weight);

    // Stage 1: GEMM (128 rows per block)
    int gemm_blocks = (n + 127) / 128;
    gemm_mma_kernel<<<gemm_blocks, 256>>>(x, wfrag, colptr, h_scratch, n);

    // Stage 2: aggregate
    int agg_blocks = (n + 7) / 8;
    aggregate_kernel<<<agg_blocks, 256>>>(h_scratch, rowptr, colind, bias,
                                          out, n);
}

// round 10
// speedup vs baseline: 1.5293x; 1.0862x over previous
#include <cuda_runtime.h>
#include <cuda_bf16.h>
#include <cuda_fp16.h>
#include <cstdint>
#include <cstring>

// GCNConv: out = D_in^{-1/2} * A * (D_out^{-1/2} * (X @ W)) + bias
// Stage 0: bake W -> fp16 frag layout (32KB global, L1-resident)
// Stage 1: zero-smem pure-fp16 mma.sync GEMM (1 MMA per n8-tile per kstep)
//          h = f16(X) @ f16(W) * out_norm -> fp16 scratch
// Stage 2: gather-aggregate (fp16 reads, fp32 accum)

#define MAX_N 100000

__device__ __half g_h[(size_t)MAX_N * 128];
// frag layout: [ntile 0..15][kstep 0..7][lane 0..31] = {fh0, fh1} (fp16x2)
__device__ uint2  g_wfrag[16 * 8 * 32];

// ---------------------------------------------------------------------------
// helpers
// ---------------------------------------------------------------------------
__device__ __forceinline__ unsigned h2u(__half2 v) {
    unsigned r;
    memcpy(&r, &v, 4);
    return r;
}

__device__ __forceinline__ unsigned cvt_f16x2(float2 v) {
    unsigned r;
    asm("cvt.rn.f16x2.f32 %0, %1, %2;" : "=r"(r) : "f"(v.y), "f"(v.x));
    return r;
}

__device__ __forceinline__ void mma_f16(float* c, const unsigned* a,
                                        unsigned b0, unsigned b1) {
    asm volatile(
        "mma.sync.aligned.m16n8k16.row.col.f32.f16.f16.f32 "
        "{%0,%1,%2,%3}, {%4,%5,%6,%7}, {%8,%9}, {%0,%1,%2,%3};"
        : "+f"(c[0]), "+f"(c[1]), "+f"(c[2]), "+f"(c[3])
        : "r"(a[0]), "r"(a[1]), "r"(a[2]), "r"(a[3]), "r"(b0), "r"(b1));
}

// ---------------------------------------------------------------------------
// Stage 0: bake W [k][n] fp32 into per-thread fp16 frag layout.
// (ntile, kstep, lane): lg=lane>>2, lt=lane&3, n = ntile*8+lg, k0=kstep*16+2lt
//   fh0 = f16x2(W[k0][n], W[k0+1][n]);   fh1 = f16x2(W[k0+8][n], W[k0+9][n])
// ---------------------------------------------------------------------------
__global__ __launch_bounds__(256) void wfrag_kernel(const float* __restrict__ w) {
    int idx = blockIdx.x * 256 + threadIdx.x;   // 0..4095
    int lane  = idx & 31;
    int kstep = (idx >> 5) & 7;
    int ntile = idx >> 8;
    int lg = lane >> 2;
    int lt = lane & 3;
    int nn = ntile * 8 + lg;
    int k0 = kstep * 16 + 2 * lt;

    float f00 = w[(k0    ) * 128 + nn];
    float f01 = w[(k0 + 1) * 128 + nn];
    float f10 = w[(k0 + 8) * 128 + nn];
    float f11 = w[(k0 + 9) * 128 + nn];

    g_wfrag[idx] = make_uint2(h2u(__floats2half2_rn(f00, f01)),
                              h2u(__floats2half2_rn(f10, f11)));
}

// ---------------------------------------------------------------------------
// Stage 1 GEMM: zero smem. Block = 128 rows, 8 warps; warp owns rows
// [wid*16, wid*16+16) x cols [0,128) = 16 n8-tiles, 1 MMA each per kstep.
// A-frags from global (each row read once per grid), B-frags from L1-resident
// g_wfrag (32KB shared by all warps on the SM).
// ---------------------------------------------------------------------------
__global__ __launch_bounds__(256, 2) void gemm_mma_kernel(
    const float* __restrict__ x,       // [n,128]
    const uint2* __restrict__ wfrag,   // baked W frags
    const int*   __restrict__ colptr,  // [n+1]
    __half*      __restrict__ h,       // [n,128]
    int n)
{
    const int tid  = threadIdx.x;
    const int wid  = tid >> 5;
    const int lane = tid & 31;
    const int lg   = lane >> 2;
    const int lt   = lane & 3;
    const int rowbase = blockIdx.x * 128 + wid * 16;

    const int r0 = rowbase + lg;       // rows r0, r0+8
    const int r1 = r0 + 8;
    const bool v0 = r0 < n, v1 = r1 < n;

    const float2* xr0 = reinterpret_cast<const float2*>(x + (size_t)r0 * 128);
    const float2* xr1 = reinterpret_cast<const float2*>(x + (size_t)r1 * 128);

    float acc[16][4];
    #pragma unroll
    for (int nt = 0; nt < 16; nt++)
        #pragma unroll
        for (int j = 0; j < 4; j++)
            acc[nt][j] = 0.f;

    const float2 z2 = make_float2(0.f, 0.f);

    // A prefetch: j0=(r0,klo) j1=(r1,klo) j2=(r0,khi) j3=(r1,khi)
    float2 pa[4];
    pa[0] = v0 ? xr0[lt]     : z2;
    pa[1] = v1 ? xr1[lt]     : z2;
    pa[2] = v0 ? xr0[lt + 4] : z2;
    pa[3] = v1 ? xr1[lt + 4] : z2;

    const uint2* wf = wfrag + lane;

    #pragma unroll
    for (int s = 0; s < 8; s++) {
        unsigned a[4];
        #pragma unroll
        for (int j = 0; j < 4; j++)
            a[j] = cvt_f16x2(pa[j]);

        if (s < 7) {
            const int kq = (s + 1) * 8 + lt;
            pa[0] = v0 ? xr0[kq]     : z2;
            pa[1] = v1 ? xr1[kq]     : z2;
            pa[2] = v0 ? xr0[kq + 4] : z2;
            pa[3] = v1 ? xr1[kq + 4] : z2;
        }

        #pragma unroll
        for (int nt = 0; nt < 16; nt++) {
            uint2 b = wf[(nt * 8 + s) * 32];
            mma_f16(acc[nt], a, b.x, b.y);
        }
    }

    // --- epilogue: scale by out_norm (1/sqrt(out-degree)), fp16 stores ---
    float s0 = 0.f, s1 = 0.f;
    if (v0) {
        float d = (float)(colptr[r0 + 1] - colptr[r0]);
        s0 = (d > 0.f) ? rsqrtf(d) : 0.f;
    }
    if (v1) {
        float d = (float)(colptr[r1 + 1] - colptr[r1]);
        s1 = (d > 0.f) ? rsqrtf(d) : 0.f;
    }

    #pragma unroll
    for (int nt = 0; nt < 16; nt++) {
        const int col = nt * 8 + 2 * lt;
        if (v0) {
            __half2 p = __floats2half2_rn(acc[nt][0] * s0, acc[nt][1] * s0);
            *reinterpret_cast<unsigned*>(&h[(size_t)r0 * 128 + col]) = h2u(p);
        }
        if (v1) {
            __half2 p = __floats2half2_rn(acc[nt][2] * s1, acc[nt][3] * s1);
            *reinterpret_cast<unsigned*>(&h[(size_t)r1 * 128 + col]) = h2u(p);
        }
    }
}

// ---------------------------------------------------------------------------
// Stage 2: aggregation. 8 nodes/block (256 thr), 32 lanes/node, uint2 fp16
// loads, fp32 accumulate.
// ---------------------------------------------------------------------------
__global__ __launch_bounds__(256) void aggregate_kernel(
    const __half* __restrict__ h,
    const int*    __restrict__ rowptr,
    const int*    __restrict__ colind,
    const float*  __restrict__ bias,
    float*        __restrict__ out,
    int n)
{
    const int node = blockIdx.x * 8 + (threadIdx.x >> 5);
    const int lane = threadIdx.x & 31;
    if (node >= n) return;

    const int beg = rowptr[node];
    const int end = rowptr[node + 1];
    const uint2* h2 = reinterpret_cast<const uint2*>(h);

    float4 acc = make_float4(0.f, 0.f, 0.f, 0.f);

    int e = beg;
    for (; e + 4 <= end; e += 4) {
        int i0 = __ldg(&colind[e + 0]);
        int i1 = __ldg(&colind[e + 1]);
        int i2 = __ldg(&colind[e + 2]);
        int i3 = __ldg(&colind[e + 3]);
        uint2 u0 = h2[(size_t)i0 * 32 + lane];
        uint2 u1 = h2[(size_t)i1 * 32 + lane];
        uint2 u2 = h2[(size_t)i2 * 32 + lane];
        uint2 u3 = h2[(size_t)i3 * 32 + lane];
        float2 f;
        f = __half22float2(*reinterpret_cast<__half2*>(&u0.x)); acc.x += f.x; acc.y += f.y;
        f = __half22float2(*reinterpret_cast<__half2*>(&u0.y)); acc.z += f.x; acc.w += f.y;
        f = __half22float2(*reinterpret_cast<__half2*>(&u1.x)); acc.x += f.x; acc.y += f.y;
        f = __half22float2(*reinterpret_cast<__half2*>(&u1.y)); acc.z += f.x; acc.w += f.y;
        f = __half22float2(*reinterpret_cast<__half2*>(&u2.x)); acc.x += f.x; acc.y += f.y;
        f = __half22float2(*reinterpret_cast<__half2*>(&u2.y)); acc.z += f.x; acc.w += f.y;
        f = __half22float2(*reinterpret_cast<__half2*>(&u3.x)); acc.x += f.x; acc.y += f.y;
        f = __half22float2(*reinterpret_cast<__half2*>(&u3.y)); acc.z += f.x; acc.w += f.y;
    }
    for (; e < end; e++) {
        int i0 = __ldg(&colind[e]);
        uint2 u0 = h2[(size_t)i0 * 32 + lane];
        float2 f;
        f = __half22float2(*reinterpret_cast<__half2*>(&u0.x)); acc.x += f.x; acc.y += f.y;
        f = __half22float2(*reinterpret_cast<__half2*>(&u0.y)); acc.z += f.x; acc.w += f.y;
    }

    float deg = (float)(end - beg);
    float s = (deg > 0.f) ? rsqrtf(deg) : 0.f;

    float4 b = reinterpret_cast<const float4*>(bias)[lane];
    float4 o;
    o.x = acc.x * s + b.x;
    o.y = acc.y * s + b.y;
    o.z = acc.z * s + b.z;
    o.w = acc.w * s + b.w;

    reinterpret_cast<float4*>(out)[(size_t)node * 32 + lane] = o;
}

// ---------------------------------------------------------------------------
// launch
// ---------------------------------------------------------------------------
extern "C" void kernel_launch(void* const* d_in, const int* in_sizes, int n_in,
                              void* d_out, int out_size)
{
    const float* x      = (const float*)d_in[0];
    const float* weight = (const float*)d_in[1];
    const float* bias   = (const float*)d_in[2];
    const int*   rowptr = (const int*)  d_in[3];
    const int*   colind = (const int*)  d_in[4];
    const int*   colptr = (const int*)  d_in[5];

    const int n = in_sizes[3] - 1;
    float* out = (float*)d_out;

    __half* h_scratch = nullptr;
    cudaGetSymbolAddress((void**)&h_scratch, g_h);
    uint2* wfrag = nullptr;
    cudaGetSymbolAddress((void**)&wfrag, g_wfrag);

    // Stage 0: bake W frags (4096 uint2)
    wfrag_kernel<<<16, 256>>>(weight);

    // Stage 1: GEMM (128 rows per block)
    int gemm_blocks = (n + 127) / 128;
    gemm_mma_kernel<<<gemm_blocks, 256>>>(x, wfrag, colptr, h_scratch, n);

    // Stage 2: aggregate
    int agg_blocks = (n + 7) / 8;
    aggregate_kernel<<<agg_blocks, 256>>>(h_scratch, rowptr, colind, bias,
                                          out, n);
}

// round 11
// speedup vs baseline: 1.6333x; 1.0680x over previous
#include <cuda_runtime.h>
#include <cuda_bf16.h>
#include <cuda_fp16.h>
#include <cstdint>
#include <cstring>

// GCNConv: out = D_in^{-1/2} * A * (D_out^{-1/2} * (X @ W)) + bias
// Stage 0: bake W -> fp16 frag layout, kstep-PAIRED uint4 (32KB, L1-resident)
// Stage 1: zero-smem pure-fp16 mma.sync GEMM (1 MMA per n8-tile per kstep)
// Stage 2: gather-aggregate, deg==16 fast path with 16-wide MLP

#define MAX_N 100000

__device__ __half g_h[(size_t)MAX_N * 128];
// frag layout: [ntile 0..15][spair 0..3][lane 0..31] =
//   {even-kstep fh0, even fh1, odd fh0, odd fh1}
__device__ uint4  g_wfrag[16 * 4 * 32];

// ---------------------------------------------------------------------------
// helpers
// ---------------------------------------------------------------------------
__device__ __forceinline__ unsigned h2u(__half2 v) {
    unsigned r;
    memcpy(&r, &v, 4);
    return r;
}

__device__ __forceinline__ unsigned cvt_f16x2(float2 v) {
    unsigned r;
    asm("cvt.rn.f16x2.f32 %0, %1, %2;" : "=r"(r) : "f"(v.y), "f"(v.x));
    return r;
}

__device__ __forceinline__ void mma_f16(float* c, const unsigned* a,
                                        unsigned b0, unsigned b1) {
    asm volatile(
        "mma.sync.aligned.m16n8k16.row.col.f32.f16.f16.f32 "
        "{%0,%1,%2,%3}, {%4,%5,%6,%7}, {%8,%9}, {%0,%1,%2,%3};"
        : "+f"(c[0]), "+f"(c[1]), "+f"(c[2]), "+f"(c[3])
        : "r"(a[0]), "r"(a[1]), "r"(a[2]), "r"(a[3]), "r"(b0), "r"(b1));
}

// ---------------------------------------------------------------------------
// Stage 0: bake W [k][n] fp32 into kstep-paired fp16 frag layout.
// (ntile, sp, lane): lg=lane>>2, lt=lane&3, n = ntile*8+lg
//   even kstep s0=2sp: k0 = s0*16 + 2lt  -> fh0 (k0,k0+1), fh1 (k0+8,k0+9)
//   odd  kstep s1=2sp+1: k1 = k0 + 16    -> fh0', fh1'
// ---------------------------------------------------------------------------
__global__ __launch_bounds__(256) void wfrag_kernel(const float* __restrict__ w) {
    int idx = blockIdx.x * 256 + threadIdx.x;   // 0..2047
    int lane = idx & 31;
    int sp   = (idx >> 5) & 3;
    int ntile = idx >> 7;
    int lg = lane >> 2;
    int lt = lane & 3;
    int nn = ntile * 8 + lg;
    int k0 = (2 * sp) * 16 + 2 * lt;

    float e00 = w[(k0    ) * 128 + nn];
    float e01 = w[(k0 + 1) * 128 + nn];
    float e10 = w[(k0 + 8) * 128 + nn];
    float e11 = w[(k0 + 9) * 128 + nn];
    float o00 = w[(k0 + 16) * 128 + nn];
    float o01 = w[(k0 + 17) * 128 + nn];
    float o10 = w[(k0 + 24) * 128 + nn];
    float o11 = w[(k0 + 25) * 128 + nn];

    g_wfrag[idx] = make_uint4(h2u(__floats2half2_rn(e00, e01)),
                              h2u(__floats2half2_rn(e10, e11)),
                              h2u(__floats2half2_rn(o00, o01)),
                              h2u(__floats2half2_rn(o10, o11)));
}

// ---------------------------------------------------------------------------
// Stage 1 GEMM: zero smem. Block = 128 rows, 8 warps; warp owns rows
// [wid*16, wid*16+16) x cols [0,128) = 16 n8-tiles.
// Loop over 4 kstep-pairs; B = one LDG.128 per (nt, pair) serving 2 MMAs.
// ---------------------------------------------------------------------------
__global__ __launch_bounds__(256, 2) void gemm_mma_kernel(
    const float* __restrict__ x,       // [n,128]
    const uint4* __restrict__ wfrag,   // baked W frags (paired)
    const int*   __restrict__ colptr,  // [n+1]
    __half*      __restrict__ h,       // [n,128]
    int n)
{
    const int tid  = threadIdx.x;
    const int wid  = tid >> 5;
    const int lane = tid & 31;
    const int lg   = lane >> 2;
    const int lt   = lane & 3;
    const int rowbase = blockIdx.x * 128 + wid * 16;

    const int r0 = rowbase + lg;       // rows r0, r0+8
    const int r1 = r0 + 8;
    const bool v0 = r0 < n, v1 = r1 < n;

    const float2* xr0 = reinterpret_cast<const float2*>(x + (size_t)r0 * 128);
    const float2* xr1 = reinterpret_cast<const float2*>(x + (size_t)r1 * 128);

    float acc[16][4];
    #pragma unroll
    for (int nt = 0; nt < 16; nt++)
        #pragma unroll
        for (int j = 0; j < 4; j++)
            acc[nt][j] = 0.f;

    const float2 z2 = make_float2(0.f, 0.f);

    // two ksteps of A in flight: pe = even kstep, po = odd kstep
    float2 pe[4], po[4];
    {
        const int kq = lt;
        pe[0] = v0 ? xr0[kq]      : z2;
        pe[1] = v1 ? xr1[kq]      : z2;
        pe[2] = v0 ? xr0[kq + 4]  : z2;
        pe[3] = v1 ? xr1[kq + 4]  : z2;
        po[0] = v0 ? xr0[kq + 8]  : z2;
        po[1] = v1 ? xr1[kq + 8]  : z2;
        po[2] = v0 ? xr0[kq + 12] : z2;
        po[3] = v1 ? xr1[kq + 12] : z2;
    }

    const uint4* wf = wfrag + lane;

    #pragma unroll
    for (int sp = 0; sp < 4; sp++) {
        unsigned ae[4], ao[4];
        #pragma unroll
        for (int j = 0; j < 4; j++) {
            ae[j] = cvt_f16x2(pe[j]);
            ao[j] = cvt_f16x2(po[j]);
        }

        if (sp < 3) {
            const int kq = (2 * sp + 2) * 8 + lt;
            pe[0] = v0 ? xr0[kq]      : z2;
            pe[1] = v1 ? xr1[kq]      : z2;
            pe[2] = v0 ? xr0[kq + 4]  : z2;
            pe[3] = v1 ? xr1[kq + 4]  : z2;
            po[0] = v0 ? xr0[kq + 8]  : z2;
            po[1] = v1 ? xr1[kq + 8]  : z2;
            po[2] = v0 ? xr0[kq + 12] : z2;
            po[3] = v1 ? xr1[kq + 12] : z2;
        }

        #pragma unroll
        for (int nt = 0; nt < 16; nt++) {
            uint4 b = wf[(nt * 4 + sp) * 32];
            mma_f16(acc[nt], ae, b.x, b.y);
            mma_f16(acc[nt], ao, b.z, b.w);
        }
    }

    // --- epilogue: scale by out_norm (1/sqrt(out-degree)), fp16 stores ---
    float s0 = 0.f, s1 = 0.f;
    if (v0) {
        float d = (float)(colptr[r0 + 1] - colptr[r0]);
        s0 = (d > 0.f) ? rsqrtf(d) : 0.f;
    }
    if (v1) {
        float d = (float)(colptr[r1 + 1] - colptr[r1]);
        s1 = (d > 0.f) ? rsqrtf(d) : 0.f;
    }

    #pragma unroll
    for (int nt = 0; nt < 16; nt++) {
        const int col = nt * 8 + 2 * lt;
        if (v0) {
            __half2 p = __floats2half2_rn(acc[nt][0] * s0, acc[nt][1] * s0);
            *reinterpret_cast<unsigned*>(&h[(size_t)r0 * 128 + col]) = h2u(p);
        }
        if (v1) {
            __half2 p = __floats2half2_rn(acc[nt][2] * s1, acc[nt][3] * s1);
            *reinterpret_cast<unsigned*>(&h[(size_t)r1 * 128 + col]) = h2u(p);
        }
    }
}

// ---------------------------------------------------------------------------
// Stage 2: aggregation. 8 nodes/block (256 thr), 32 lanes/node.
// deg==16 fast path: 4x LDG.128 on colind, then 16 row-gathers all in flight.
// ---------------------------------------------------------------------------
__global__ __launch_bounds__(256) void aggregate_kernel(
    const __half* __restrict__ h,
    const int*    __restrict__ rowptr,
    const int*    __restrict__ colind,
    const float*  __restrict__ bias,
    float*        __restrict__ out,
    int n)
{
    const int node = blockIdx.x * 8 + (threadIdx.x >> 5);
    const int lane = threadIdx.x & 31;
    if (node >= n) return;

    const int beg = rowptr[node];
    const int end = rowptr[node + 1];
    const uint2* h2 = reinterpret_cast<const uint2*>(h);

    float4 a0 = make_float4(0.f, 0.f, 0.f, 0.f);
    float4 a1 = make_float4(0.f, 0.f, 0.f, 0.f);

    if (end - beg == 16 && (beg & 3) == 0) {
        const int4* cp = reinterpret_cast<const int4*>(colind + beg);
        int4 c0 = __ldg(cp + 0);
        int4 c1 = __ldg(cp + 1);
        int4 c2 = __ldg(cp + 2);
        int4 c3 = __ldg(cp + 3);
        int idx[16] = {c0.x, c0.y, c0.z, c0.w, c1.x, c1.y, c1.z, c1.w,
                       c2.x, c2.y, c2.z, c2.w, c3.x, c3.y, c3.z, c3.w};
        uint2 v[16];
        #pragma unroll
        for (int i = 0; i < 16; i++)
            v[i] = h2[(size_t)idx[i] * 32 + lane];
        #pragma unroll
        for (int i = 0; i < 16; i += 2) {
            float2 f;
            f = __half22float2(*reinterpret_cast<__half2*>(&v[i].x));
            a0.x += f.x; a0.y += f.y;
            f = __half22float2(*reinterpret_cast<__half2*>(&v[i].y));
            a0.z += f.x; a0.w += f.y;
            f = __half22float2(*reinterpret_cast<__half2*>(&v[i+1].x));
            a1.x += f.x; a1.y += f.y;
            f = __half22float2(*reinterpret_cast<__half2*>(&v[i+1].y));
            a1.z += f.x; a1.w += f.y;
        }
    } else {
        for (int e = beg; e < end; e++) {
            int i0 = __ldg(&colind[e]);
            uint2 u0 = h2[(size_t)i0 * 32 + lane];
            float2 f;
            f = __half22float2(*reinterpret_cast<__half2*>(&u0.x));
            a0.x += f.x; a0.y += f.y;
            f = __half22float2(*reinterpret_cast<__half2*>(&u0.y));
            a0.z += f.x; a0.w += f.y;
        }
    }

    float4 acc;
    acc.x = a0.x + a1.x;
    acc.y = a0.y + a1.y;
    acc.z = a0.z + a1.z;
    acc.w = a0.w + a1.w;

    float deg = (float)(end - beg);
    float s = (deg > 0.f) ? rsqrtf(deg) : 0.f;

    float4 b = reinterpret_cast<const float4*>(bias)[lane];
    float4 o;
    o.x = acc.x * s + b.x;
    o.y = acc.y * s + b.y;
    o.z = acc.z * s + b.z;
    o.w = acc.w * s + b.w;

    reinterpret_cast<float4*>(out)[(size_t)node * 32 + lane] = o;
}

// ---------------------------------------------------------------------------
// launch
// ---------------------------------------------------------------------------
extern "C" void kernel_launch(void* const* d_in, const int* in_sizes, int n_in,
                              void* d_out, int out_size)
{
    const float* x      = (const float*)d_in[0];
    const float* weight = (const float*)d_in[1];
    const float* bias   = (const float*)d_in[2];
    const int*   rowptr = (const int*)  d_in[3];
    const int*   colind = (const int*)  d_in[4];
    const int*   colptr = (const int*)  d_in[5];

    const int n = in_sizes[3] - 1;
    float* out = (float*)d_out;

    __half* h_scratch = nullptr;
    cudaGetSymbolAddress((void**)&h_scratch, g_h);
    uint4* wfrag = nullptr;
    cudaGetSymbolAddress((void**)&wfrag, g_wfrag);

    // Stage 0: bake W frags (2048 uint4)
    wfrag_kernel<<<8, 256>>>(weight);

    // Stage 1: GEMM (128 rows per block)
    int gemm_blocks = (n + 127) / 128;
    gemm_mma_kernel<<<gemm_blocks, 256>>>(x, wfrag, colptr, h_scratch, n);

    // Stage 2: aggregate
    int agg_blocks = (n + 7) / 8;
    aggregate_kernel<<<agg_blocks, 256>>>(h_scratch, rowptr, colind, bias,
                                          out, n);
}